// round 2
// baseline (speedup 1.0000x reference)
#include <cuda_runtime.h>
#include <cuda_bf16.h>
#include <math.h>

// ---------------- problem constants ----------------
constexpr int kD   = 1024;
constexpr int kHD  = 64;
constexpr int kNH  = 16;
constexpr int kH   = 16;   // routing heads
constexpr int kKH  = 8;
constexpr int kN   = 128;  // tokens per block
constexpr int kE   = 4096;
constexpr int kRE  = 4;
constexpr int kDE  = 4;
constexpr int kET  = 16;   // RE*DE
constexpr int kS   = 2048;
constexpr int kT   = 2048;
constexpr int kBC  = 16;   // T / N
constexpr float kEPS   = 1e-5f;
constexpr float kTHETA = 10000.0f;

// ---------------- device scratch ----------------
__device__ float g_xnorm[kT * kD];        // rmsnorm(x_input)
__device__ float g_qkv  [kT * 3 * kD];    // qkv
__device__ float g_q    [kNH * kS * kHD]; // rope'd q, (h, s, d)
__device__ float g_k    [kNH * kS * kHD]; // rope'd k, (h, s, d)
__device__ float g_attn [kT * kD];        // attention output, (t, h*64+d)
__device__ float g_proj [kT * kD];        // attn out-proj
__device__ float g_resid[kT * kD];        // x_ffn_input
__device__ float g_xf   [kT * kD];        // rmsnorm(x_ffn_input)
__device__ float g_G    [kT * kET * 8];   // gathered routing dots per (t, j, h2)
__device__ float g_w    [kT * kET];       // combined gate weights

// ---------------- helpers ----------------
__device__ __forceinline__ float block_reduce_sum_256(float v) {
    __shared__ float red[8];
    #pragma unroll
    for (int o = 16; o; o >>= 1) v += __shfl_xor_sync(0xffffffffu, v, o);
    if ((threadIdx.x & 31) == 0) red[threadIdx.x >> 5] = v;
    __syncthreads();
    float s = 0.f;
    #pragma unroll
    for (int i = 0; i < 8; i++) s += red[i];
    __syncthreads();
    return s;
}

// ---------------- K1: rmsnorm (block per token, 256 thr, 1 float4/thr) ----------------
__global__ void rmsnorm_kernel(const float* __restrict__ x,
                               const float* __restrict__ w,
                               float* __restrict__ out) {
    const int t = blockIdx.x;
    const float4 v = ((const float4*)(x + t * kD))[threadIdx.x];
    float ss = v.x*v.x + v.y*v.y + v.z*v.z + v.w*v.w;
    ss = block_reduce_sum_256(ss);
    const float scale = rsqrtf(ss * (1.0f / kD) + kEPS);
    const float4 wv = ((const float4*)w)[threadIdx.x];
    float4 o;
    o.x = v.x * scale * wv.x; o.y = v.y * scale * wv.y;
    o.z = v.z * scale * wv.z; o.w = v.w * scale * wv.w;
    ((float4*)(out + t * kD))[threadIdx.x] = o;
}

// ---------------- K2: residual add + rmsnorm ----------------
__global__ void resid_rmsnorm_kernel(const float* __restrict__ a,
                                     const float* __restrict__ b,
                                     const float* __restrict__ w,
                                     float* __restrict__ resid,
                                     float* __restrict__ xf) {
    const int t = blockIdx.x;
    const float4 va = ((const float4*)(a + t * kD))[threadIdx.x];
    const float4 vb = ((const float4*)(b + t * kD))[threadIdx.x];
    float4 v;
    v.x = va.x + vb.x; v.y = va.y + vb.y; v.z = va.z + vb.z; v.w = va.w + vb.w;
    ((float4*)(resid + t * kD))[threadIdx.x] = v;
    float ss = v.x*v.x + v.y*v.y + v.z*v.z + v.w*v.w;
    ss = block_reduce_sum_256(ss);
    const float scale = rsqrtf(ss * (1.0f / kD) + kEPS);
    const float4 wv = ((const float4*)w)[threadIdx.x];
    float4 o;
    o.x = v.x * scale * wv.x; o.y = v.y * scale * wv.y;
    o.z = v.z * scale * wv.z; o.w = v.w * scale * wv.w;
    ((float4*)(xf + t * kD))[threadIdx.x] = o;
}

// ---------------- K3: SGEMM 128x128x8, 256 threads, TM=TN=8 ----------------
__global__ __launch_bounds__(256) void sgemm128(int M, int N, int K,
                                                const float* __restrict__ A,
                                                const float* __restrict__ B,
                                                float* __restrict__ C) {
    constexpr int BM = 128, BN = 128, BK = 8, TM = 8, TN = 8;
    __shared__ float As[BK * BM];  // transposed
    __shared__ float Bs[BK * BN];
    const int tid = threadIdx.x;
    const int threadCol = tid % (BN / TN);  // 16
    const int threadRow = tid / (BN / TN);  // 16
    A += blockIdx.y * BM * K;
    B += blockIdx.x * BN;
    C += blockIdx.y * BM * N + blockIdx.x * BN;
    const int innerRowA = tid / 2;   // BK/4 = 2 cols of float4
    const int innerColA = tid % 2;
    const int innerRowB = tid / 32;  // BN/4 = 32
    const int innerColB = tid % 32;
    float acc[TM * TN];
    #pragma unroll
    for (int i = 0; i < TM * TN; i++) acc[i] = 0.f;
    float regM[TM], regN[TN];
    for (int bk = 0; bk < K; bk += BK) {
        const float4 a4 = *(const float4*)(A + innerRowA * K + innerColA * 4);
        As[(innerColA * 4 + 0) * BM + innerRowA] = a4.x;
        As[(innerColA * 4 + 1) * BM + innerRowA] = a4.y;
        As[(innerColA * 4 + 2) * BM + innerRowA] = a4.z;
        As[(innerColA * 4 + 3) * BM + innerRowA] = a4.w;
        *(float4*)(Bs + innerRowB * BN + innerColB * 4) =
            *(const float4*)(B + innerRowB * N + innerColB * 4);
        __syncthreads();
        A += BK;
        B += BK * N;
        #pragma unroll
        for (int k = 0; k < BK; k++) {
            #pragma unroll
            for (int i = 0; i < TM; i++) regM[i] = As[k * BM + threadRow * TM + i];
            #pragma unroll
            for (int i = 0; i < TN; i++) regN[i] = Bs[k * BN + threadCol * TN + i];
            #pragma unroll
            for (int m = 0; m < TM; m++)
                #pragma unroll
                for (int n = 0; n < TN; n++)
                    acc[m * TN + n] += regM[m] * regN[n];
        }
        __syncthreads();
    }
    #pragma unroll
    for (int m = 0; m < TM; m++) {
        #pragma unroll
        for (int n = 0; n < TN; n += 4) {
            float4 o;
            o.x = acc[m * TN + n + 0];
            o.y = acc[m * TN + n + 1];
            o.z = acc[m * TN + n + 2];
            o.w = acc[m * TN + n + 3];
            *(float4*)(C + (threadRow * TM + m) * N + threadCol * TN + n) = o;
        }
    }
}

// ---------------- K4: l2norm + rope for q and k ----------------
// block per token (256 thr = 8 warps). warp w handles heads 2w, 2w+1 for q and k.
// lane l owns dims l and l+32 (the rope pair).
__global__ void qkprep_kernel(const float* __restrict__ qkv,
                              float* __restrict__ qout,
                              float* __restrict__ kout) {
    const int t = blockIdx.x;
    const int warp = threadIdx.x >> 5;
    const int lane = threadIdx.x & 31;
    const float inv_freq = powf(kTHETA, -(float)lane / 32.0f);
    const float freq = (float)t * inv_freq;
    const float c = cosf(freq), sn = sinf(freq);
    #pragma unroll
    for (int hh = 0; hh < 2; hh++) {
        const int h = warp * 2 + hh;
        #pragma unroll
        for (int qk = 0; qk < 2; qk++) {
            const float* src = qkv + t * (3 * kD) + qk * kD + h * kHD;
            float v1 = src[lane];
            float v2 = src[lane + 32];
            float ss = v1 * v1 + v2 * v2;
            #pragma unroll
            for (int o = 16; o; o >>= 1) ss += __shfl_xor_sync(0xffffffffu, ss, o);
            const float inv = 1.0f / fmaxf(sqrtf(ss), kEPS);
            v1 *= inv; v2 *= inv;
            const float o1 =  v1 * c + v2 * sn;
            const float o2 = -v1 * sn + v2 * c;
            float* dst = (qk ? kout : qout) + (h * kS + t) * kHD;
            dst[lane] = o1;
            dst[lane + 32] = o2;
        }
    }
}

// ---------------- K5: causal attention, flash-style, 1 query/thread ----------------
constexpr int kQB = 64;
constexpr int kKB = 32;
__global__ __launch_bounds__(kQB) void attn_kernel(const float* __restrict__ q,
                                                   const float* __restrict__ k,
                                                   const float* __restrict__ qkv,
                                                   float* __restrict__ out) {
    const int h  = blockIdx.x;
    const int qb = blockIdx.y;
    const int qi = qb * kQB + threadIdx.x;
    __shared__ float4 Ks[kKB * 16];
    __shared__ float4 Vs[kKB * 16];
    float4 q4[16], o4[16];
    const float4* qp = (const float4*)(q + (h * kS + qi) * kHD);
    #pragma unroll
    for (int i = 0; i < 16; i++) {
        q4[i] = qp[i];
        o4[i] = make_float4(0.f, 0.f, 0.f, 0.f);
    }
    float m = -1e30f, l = 0.f;
    const int ntiles = qb * 2 + 2;  // (qb*64+64)/32
    for (int kt = 0; kt < ntiles; kt++) {
        const int base = kt * kKB;
        #pragma unroll
        for (int r = 0; r < 8; r++) {
            const int idx = r * kQB + threadIdx.x;  // 0..511
            const int row = idx >> 4, col = idx & 15;
            Ks[idx] = ((const float4*)(k + (h * kS + base + row) * kHD))[col];
            Vs[idx] = ((const float4*)(qkv + (base + row) * (3 * kD) + 2 * kD + h * kHD))[col];
        }
        __syncthreads();
        const int jmax = min(kKB, qi - base + 1);
        for (int j = 0; j < jmax; j++) {
            float s = 0.f;
            #pragma unroll
            for (int i = 0; i < 16; i++) {
                const float4 kv = Ks[j * 16 + i];
                s += q4[i].x * kv.x + q4[i].y * kv.y + q4[i].z * kv.z + q4[i].w * kv.w;
            }
            s *= 0.125f;
            const float mn = fmaxf(m, s);
            const float corr = __expf(m - mn);
            const float p = __expf(s - mn);
            l = l * corr + p;
            #pragma unroll
            for (int i = 0; i < 16; i++) {
                const float4 vv = Vs[j * 16 + i];
                o4[i].x = o4[i].x * corr + p * vv.x;
                o4[i].y = o4[i].y * corr + p * vv.y;
                o4[i].z = o4[i].z * corr + p * vv.z;
                o4[i].w = o4[i].w * corr + p * vv.w;
            }
            m = mn;
        }
        __syncthreads();
    }
    const float inv = 1.0f / l;
    float4* op = (float4*)(out + qi * kD + h * kHD);
    #pragma unroll
    for (int i = 0; i < 16; i++)
        op[i] = make_float4(o4[i].x * inv, o4[i].y * inv, o4[i].z * inv, o4[i].w * inv);
}

// ---------------- K6: gathered routing GEMM ----------------
// block per (c, j): G[t, j, h2] = sum_d xf[t,d] * keys[h2, d, e_j]
__global__ __launch_bounds__(256) void route_gemm_kernel(const float* __restrict__ xf,
                                                         const float* __restrict__ keys,
                                                         const int* __restrict__ indices,
                                                         float* __restrict__ G) {
    const int j = blockIdx.x;
    const int c = blockIdx.y;
    const int e = indices[c * kET + j];
    __shared__ float4 kcol[8 * 256];  // [h2][d4] : 8 heads x 1024 floats
    #pragma unroll
    for (int r = 0; r < 8; r++) {
        const int idx = r * 256 + threadIdx.x;
        const int h2 = idx >> 8;
        const int d4 = idx & 255;
        const float* base = keys + (size_t)h2 * kD * kE + (size_t)(d4 * 4) * kE + e;
        float4 v;
        v.x = __ldg(base);
        v.y = __ldg(base + kE);
        v.z = __ldg(base + 2 * kE);
        v.w = __ldg(base + 3 * kE);
        kcol[idx] = v;
    }
    __syncthreads();
    const int warp = threadIdx.x >> 5;
    const int lane = threadIdx.x & 31;
    for (int tt = 0; tt < 16; tt++) {
        const int t = c * kN + warp * 16 + tt;
        float acc[8];
        #pragma unroll
        for (int i = 0; i < 8; i++) acc[i] = 0.f;
        const float4* xp = (const float4*)(xf + t * kD);
        #pragma unroll
        for (int i = 0; i < 8; i++) {
            const float4 xv = xp[i * 32 + lane];
            #pragma unroll
            for (int h2 = 0; h2 < 8; h2++) {
                const float4 kv = kcol[h2 * 256 + i * 32 + lane];
                acc[h2] += xv.x * kv.x + xv.y * kv.y + xv.z * kv.z + xv.w * kv.w;
            }
        }
        #pragma unroll
        for (int h2 = 0; h2 < 8; h2++) {
            float s = acc[h2];
            #pragma unroll
            for (int o = 16; o; o >>= 1) s += __shfl_xor_sync(0xffffffffu, s, o);
            if (lane == 0) G[((size_t)t * kET + j) * 8 + h2] = s;
        }
    }
}

// ---------------- K7: combine gate weights ----------------
__global__ void combine_kernel(const float* __restrict__ G,
                               const float* __restrict__ scores,
                               const int* __restrict__ indices,
                               const float* __restrict__ head_probs,
                               const float* __restrict__ score_probs,
                               float* __restrict__ wbuf) {
    const int tj = blockIdx.x * blockDim.x + threadIdx.x;  // T*ET
    if (tj >= kT * kET) return;
    const int t = tj >> 4, j = tj & 15;
    const int c = t >> 7;
    const int e = indices[c * kET + j];
    const int r = j >> 2;
    const float* sp0 = score_probs + ((size_t)(0 * kRE + r) * kE + e) * kH;
    const float* sp1 = score_probs + ((size_t)(1 * kRE + r) * kE + e) * kH + (size_t)0;
    // note: full offset for s=1 is (kRE*kE*kH) extra:
    sp1 = score_probs + (size_t)kRE * kE * kH + ((size_t)r * kE + e) * kH;
    const float* hp = head_probs + ((size_t)r * kE + e) * kH;
    const float* sc = scores + ((size_t)t * kET + j) * kH;
    const float* g = G + (size_t)tj * 8;
    float acc = 0.f;
    #pragma unroll
    for (int h = 0; h < kH; h++) {
        const float x = sp0[h] * g[h >> 1] + sp1[h] * sc[h];
        const float sig = 1.0f / (1.0f + __expf(-x));
        acc += sig * hp[h];
    }
    wbuf[tj] = acc;
}

// ---------------- K8: expert FFN + final residual ----------------
// block per token. warp w computes dots for j = 2w, 2w+1 (h0 and h1 each).
__global__ __launch_bounds__(256) void expert_kernel(const float* __restrict__ xf,
                                                     const float* __restrict__ experts,
                                                     const int* __restrict__ indices,
                                                     const float* __restrict__ wbuf,
                                                     const float* __restrict__ resid,
                                                     float* __restrict__ out) {
    const int t = blockIdx.x;
    const int c = t >> 7;
    __shared__ int es[kET];
    __shared__ float h01[2 * kET];
    __shared__ float act_s[kET];
    if (threadIdx.x < kET) es[threadIdx.x] = indices[c * kET + threadIdx.x];
    __syncthreads();
    const int warp = threadIdx.x >> 5;
    const int lane = threadIdx.x & 31;
    const float4* xp = (const float4*)(xf + t * kD);
    #pragma unroll
    for (int jj = 0; jj < 2; jj++) {
        const int j = warp * 2 + jj;
        const int e = es[j];
        const float4* w0 = (const float4*)(experts + ((size_t)0 * kE + e) * kD);
        const float4* w1 = (const float4*)(experts + ((size_t)1 * kE + e) * kD);
        float a0 = 0.f, a1 = 0.f;
        #pragma unroll
        for (int i = 0; i < 8; i++) {
            const float4 xv = xp[i * 32 + lane];
            const float4 v0 = w0[i * 32 + lane];
            const float4 v1 = w1[i * 32 + lane];
            a0 += xv.x * v0.x + xv.y * v0.y + xv.z * v0.z + xv.w * v0.w;
            a1 += xv.x * v1.x + xv.y * v1.y + xv.z * v1.z + xv.w * v1.w;
        }
        #pragma unroll
        for (int o = 16; o; o >>= 1) {
            a0 += __shfl_xor_sync(0xffffffffu, a0, o);
            a1 += __shfl_xor_sync(0xffffffffu, a1, o);
        }
        if (lane == 0) {
            h01[j] = a0;
            h01[kET + j] = a1;
        }
    }
    __syncthreads();
    if (threadIdx.x < kET) {
        const int j = threadIdx.x;
        const float h0 = h01[j], h1 = h01[kET + j];
        const float silu = h0 / (1.0f + __expf(-h0));
        act_s[j] = silu * h1 * wbuf[t * kET + j];
    }
    __syncthreads();
    float4 acc = ((const float4*)(resid + t * kD))[threadIdx.x];
    #pragma unroll
    for (int j = 0; j < kET; j++) {
        const float a = act_s[j];
        const float4 wv = ((const float4*)(experts + ((size_t)2 * kE + es[j]) * kD))[threadIdx.x];
        acc.x += a * wv.x; acc.y += a * wv.y; acc.z += a * wv.z; acc.w += a * wv.w;
    }
    ((float4*)(out + t * kD))[threadIdx.x] = acc;
}

// ---------------- launch ----------------
extern "C" void kernel_launch(void* const* d_in, const int* in_sizes, int n_in,
                              void* d_out, int out_size) {
    const float* x_input     = (const float*)d_in[0];
    const int*   indices     = (const int*)  d_in[1];
    const float* scores      = (const float*)d_in[2];
    const float* attn_w      = (const float*)d_in[3];
    const float* attn_out_w  = (const float*)d_in[4];
    const float* attn_norm_w = (const float*)d_in[5];
    const float* ffn_norm_w  = (const float*)d_in[6];
    const float* ffn_experts = (const float*)d_in[7];
    const float* keys        = (const float*)d_in[8];
    const float* head_probs  = (const float*)d_in[9];
    const float* score_probs = (const float*)d_in[10];
    float* out = (float*)d_out;

    float *xnorm, *qkv, *qr, *kr, *attn, *proj, *resid, *xf, *G, *wb;
    cudaGetSymbolAddress((void**)&xnorm, g_xnorm);
    cudaGetSymbolAddress((void**)&qkv,   g_qkv);
    cudaGetSymbolAddress((void**)&qr,    g_q);
    cudaGetSymbolAddress((void**)&kr,    g_k);
    cudaGetSymbolAddress((void**)&attn,  g_attn);
    cudaGetSymbolAddress((void**)&proj,  g_proj);
    cudaGetSymbolAddress((void**)&resid, g_resid);
    cudaGetSymbolAddress((void**)&xf,    g_xf);
    cudaGetSymbolAddress((void**)&G,     g_G);
    cudaGetSymbolAddress((void**)&wb,    g_w);

    rmsnorm_kernel<<<kT, 256>>>(x_input, attn_norm_w, xnorm);
    sgemm128<<<dim3(3 * kD / 128, kT / 128), 256>>>(kT, 3 * kD, kD, xnorm, attn_w, qkv);
    qkprep_kernel<<<kT, 256>>>(qkv, qr, kr);
    attn_kernel<<<dim3(kNH, kS / kQB), kQB>>>(qr, kr, qkv, attn);
    sgemm128<<<dim3(kD / 128, kT / 128), 256>>>(kT, kD, kD, attn, attn_out_w, proj);
    resid_rmsnorm_kernel<<<kT, 256>>>(proj, x_input, ffn_norm_w, resid, xf);
    route_gemm_kernel<<<dim3(kET, kBC), 256>>>(xf, keys, indices, G);
    combine_kernel<<<(kT * kET + 255) / 256, 256>>>(G, scores, indices, head_probs, score_probs, wb);
    expert_kernel<<<kT, 256>>>(xf, ffn_experts, indices, wb, resid, out);
}

// round 3
// speedup vs baseline: 1.0013x; 1.0013x over previous
#include <cuda_runtime.h>
#include <cuda_bf16.h>
#include <math.h>

// ---------------- problem constants ----------------
constexpr int kD   = 1024;
constexpr int kHD  = 64;
constexpr int kNH  = 16;
constexpr int kH   = 16;   // routing heads
constexpr int kKH  = 8;
constexpr int kN   = 128;  // tokens per block
constexpr int kE   = 4096;
constexpr int kRE  = 4;
constexpr int kDE  = 4;
constexpr int kET  = 16;   // RE*DE
constexpr int kS   = 2048;
constexpr int kT   = 2048;
constexpr int kBC  = 16;   // T / N
constexpr float kEPS   = 1e-5f;
constexpr float kTHETA = 10000.0f;

// ---------------- device scratch ----------------
__device__ float g_xnorm[kT * kD];        // rmsnorm(x_input)
__device__ float g_qkv  [kT * 3 * kD];    // qkv
__device__ float g_q    [kNH * kS * kHD]; // rope'd q, (h, s, d)
__device__ float g_k    [kNH * kS * kHD]; // rope'd k, (h, s, d)
__device__ float g_attn [kT * kD];        // attention output, (t, h*64+d)
__device__ float g_proj [kT * kD];        // attn out-proj
__device__ float g_resid[kT * kD];        // x_ffn_input
__device__ float g_xf   [kT * kD];        // rmsnorm(x_ffn_input)
__device__ float g_G    [kT * kET * 8];   // gathered routing dots per (t, j, h2)
__device__ float g_w    [kT * kET];       // combined gate weights

// ---------------- helpers ----------------
__device__ __forceinline__ float block_reduce_sum_256(float v) {
    __shared__ float red[8];
    #pragma unroll
    for (int o = 16; o; o >>= 1) v += __shfl_xor_sync(0xffffffffu, v, o);
    if ((threadIdx.x & 31) == 0) red[threadIdx.x >> 5] = v;
    __syncthreads();
    float s = 0.f;
    #pragma unroll
    for (int i = 0; i < 8; i++) s += red[i];
    __syncthreads();
    return s;
}

// ---------------- K1: rmsnorm (block per token, 256 thr, 1 float4/thr) ----------------
__global__ void rmsnorm_kernel(const float* __restrict__ x,
                               const float* __restrict__ w,
                               float* __restrict__ out) {
    const int t = blockIdx.x;
    const float4 v = ((const float4*)(x + t * kD))[threadIdx.x];
    float ss = v.x*v.x + v.y*v.y + v.z*v.z + v.w*v.w;
    ss = block_reduce_sum_256(ss);
    const float scale = rsqrtf(ss * (1.0f / kD) + kEPS);
    const float4 wv = ((const float4*)w)[threadIdx.x];
    float4 o;
    o.x = v.x * scale * wv.x; o.y = v.y * scale * wv.y;
    o.z = v.z * scale * wv.z; o.w = v.w * scale * wv.w;
    ((float4*)(out + t * kD))[threadIdx.x] = o;
}

// ---------------- K2: residual add + rmsnorm ----------------
__global__ void resid_rmsnorm_kernel(const float* __restrict__ a,
                                     const float* __restrict__ b,
                                     const float* __restrict__ w,
                                     float* __restrict__ resid,
                                     float* __restrict__ xf) {
    const int t = blockIdx.x;
    const float4 va = ((const float4*)(a + t * kD))[threadIdx.x];
    const float4 vb = ((const float4*)(b + t * kD))[threadIdx.x];
    float4 v;
    v.x = va.x + vb.x; v.y = va.y + vb.y; v.z = va.z + vb.z; v.w = va.w + vb.w;
    ((float4*)(resid + t * kD))[threadIdx.x] = v;
    float ss = v.x*v.x + v.y*v.y + v.z*v.z + v.w*v.w;
    ss = block_reduce_sum_256(ss);
    const float scale = rsqrtf(ss * (1.0f / kD) + kEPS);
    const float4 wv = ((const float4*)w)[threadIdx.x];
    float4 o;
    o.x = v.x * scale * wv.x; o.y = v.y * scale * wv.y;
    o.z = v.z * scale * wv.z; o.w = v.w * scale * wv.w;
    ((float4*)(xf + t * kD))[threadIdx.x] = o;
}

// ---------------- K3: SGEMM 128x128x8, 256 threads, TM=TN=8 ----------------
__global__ __launch_bounds__(256) void sgemm128(int M, int N, int K,
                                                const float* __restrict__ A,
                                                const float* __restrict__ B,
                                                float* __restrict__ C) {
    constexpr int BM = 128, BN = 128, BK = 8, TM = 8, TN = 8;
    __shared__ float As[BK * BM];  // transposed
    __shared__ float Bs[BK * BN];
    const int tid = threadIdx.x;
    const int threadCol = tid % (BN / TN);  // 16
    const int threadRow = tid / (BN / TN);  // 16
    A += blockIdx.y * BM * K;
    B += blockIdx.x * BN;
    C += blockIdx.y * BM * N + blockIdx.x * BN;
    const int innerRowA = tid / 2;   // BK/4 = 2 cols of float4
    const int innerColA = tid % 2;
    const int innerRowB = tid / 32;  // BN/4 = 32
    const int innerColB = tid % 32;
    float acc[TM * TN];
    #pragma unroll
    for (int i = 0; i < TM * TN; i++) acc[i] = 0.f;
    float regM[TM], regN[TN];
    for (int bk = 0; bk < K; bk += BK) {
        const float4 a4 = *(const float4*)(A + innerRowA * K + innerColA * 4);
        As[(innerColA * 4 + 0) * BM + innerRowA] = a4.x;
        As[(innerColA * 4 + 1) * BM + innerRowA] = a4.y;
        As[(innerColA * 4 + 2) * BM + innerRowA] = a4.z;
        As[(innerColA * 4 + 3) * BM + innerRowA] = a4.w;
        *(float4*)(Bs + innerRowB * BN + innerColB * 4) =
            *(const float4*)(B + innerRowB * N + innerColB * 4);
        __syncthreads();
        A += BK;
        B += BK * N;
        #pragma unroll
        for (int k = 0; k < BK; k++) {
            #pragma unroll
            for (int i = 0; i < TM; i++) regM[i] = As[k * BM + threadRow * TM + i];
            #pragma unroll
            for (int i = 0; i < TN; i++) regN[i] = Bs[k * BN + threadCol * TN + i];
            #pragma unroll
            for (int m = 0; m < TM; m++)
                #pragma unroll
                for (int n = 0; n < TN; n++)
                    acc[m * TN + n] += regM[m] * regN[n];
        }
        __syncthreads();
    }
    #pragma unroll
    for (int m = 0; m < TM; m++) {
        #pragma unroll
        for (int n = 0; n < TN; n += 4) {
            float4 o;
            o.x = acc[m * TN + n + 0];
            o.y = acc[m * TN + n + 1];
            o.z = acc[m * TN + n + 2];
            o.w = acc[m * TN + n + 3];
            *(float4*)(C + (threadRow * TM + m) * N + threadCol * TN + n) = o;
        }
    }
}

// ---------------- K4: l2norm + rope for q and k ----------------
// block per token (256 thr = 8 warps). warp w handles heads 2w, 2w+1 for q and k.
// lane l owns dims l and l+32 (the rope pair).
__global__ void qkprep_kernel(const float* __restrict__ qkv,
                              float* __restrict__ qout,
                              float* __restrict__ kout) {
    const int t = blockIdx.x;
    const int warp = threadIdx.x >> 5;
    const int lane = threadIdx.x & 31;
    const float inv_freq = powf(kTHETA, -(float)lane / 32.0f);
    const float freq = (float)t * inv_freq;
    const float c = cosf(freq), sn = sinf(freq);
    #pragma unroll
    for (int hh = 0; hh < 2; hh++) {
        const int h = warp * 2 + hh;
        #pragma unroll
        for (int qk = 0; qk < 2; qk++) {
            const float* src = qkv + t * (3 * kD) + qk * kD + h * kHD;
            float v1 = src[lane];
            float v2 = src[lane + 32];
            float ss = v1 * v1 + v2 * v2;
            #pragma unroll
            for (int o = 16; o; o >>= 1) ss += __shfl_xor_sync(0xffffffffu, ss, o);
            const float inv = 1.0f / fmaxf(sqrtf(ss), kEPS);
            v1 *= inv; v2 *= inv;
            const float o1 =  v1 * c + v2 * sn;
            const float o2 = -v1 * sn + v2 * c;
            float* dst = (qk ? kout : qout) + (h * kS + t) * kHD;
            dst[lane] = o1;
            dst[lane + 32] = o2;
        }
    }
}

// ---------------- K5: causal attention, flash-style, 1 query/thread ----------------
constexpr int kQB = 64;
constexpr int kKB = 32;
__global__ __launch_bounds__(kQB) void attn_kernel(const float* __restrict__ q,
                                                   const float* __restrict__ k,
                                                   const float* __restrict__ qkv,
                                                   float* __restrict__ out) {
    const int h  = blockIdx.x;
    const int qb = blockIdx.y;
    const int qi = qb * kQB + threadIdx.x;
    __shared__ float4 Ks[kKB * 16];
    __shared__ float4 Vs[kKB * 16];
    float4 q4[16], o4[16];
    const float4* qp = (const float4*)(q + (h * kS + qi) * kHD);
    #pragma unroll
    for (int i = 0; i < 16; i++) {
        q4[i] = qp[i];
        o4[i] = make_float4(0.f, 0.f, 0.f, 0.f);
    }
    float m = -1e30f, l = 0.f;
    const int ntiles = qb * 2 + 2;  // (qb*64+64)/32
    for (int kt = 0; kt < ntiles; kt++) {
        const int base = kt * kKB;
        #pragma unroll
        for (int r = 0; r < 8; r++) {
            const int idx = r * kQB + threadIdx.x;  // 0..511
            const int row = idx >> 4, col = idx & 15;
            Ks[idx] = ((const float4*)(k + (h * kS + base + row) * kHD))[col];
            Vs[idx] = ((const float4*)(qkv + (base + row) * (3 * kD) + 2 * kD + h * kHD))[col];
        }
        __syncthreads();
        const int jmax = min(kKB, qi - base + 1);
        for (int j = 0; j < jmax; j++) {
            float s = 0.f;
            #pragma unroll
            for (int i = 0; i < 16; i++) {
                const float4 kv = Ks[j * 16 + i];
                s += q4[i].x * kv.x + q4[i].y * kv.y + q4[i].z * kv.z + q4[i].w * kv.w;
            }
            s *= 0.125f;
            const float mn = fmaxf(m, s);
            const float corr = __expf(m - mn);
            const float p = __expf(s - mn);
            l = l * corr + p;
            #pragma unroll
            for (int i = 0; i < 16; i++) {
                const float4 vv = Vs[j * 16 + i];
                o4[i].x = o4[i].x * corr + p * vv.x;
                o4[i].y = o4[i].y * corr + p * vv.y;
                o4[i].z = o4[i].z * corr + p * vv.z;
                o4[i].w = o4[i].w * corr + p * vv.w;
            }
            m = mn;
        }
        __syncthreads();
    }
    const float inv = 1.0f / l;
    float4* op = (float4*)(out + qi * kD + h * kHD);
    #pragma unroll
    for (int i = 0; i < 16; i++)
        op[i] = make_float4(o4[i].x * inv, o4[i].y * inv, o4[i].z * inv, o4[i].w * inv);
}

// ---------------- K6: gathered routing GEMM ----------------
// block per (c, j): G[t, j, h2] = sum_d xf[t,d] * keys[h2, d, e_j]
__global__ __launch_bounds__(256) void route_gemm_kernel(const float* __restrict__ xf,
                                                         const float* __restrict__ keys,
                                                         const int* __restrict__ indices,
                                                         float* __restrict__ G) {
    const int j = blockIdx.x;
    const int c = blockIdx.y;
    const int e = indices[c * kET + j];
    __shared__ float4 kcol[8 * 256];  // [h2][d4] : 8 heads x 1024 floats
    #pragma unroll
    for (int r = 0; r < 8; r++) {
        const int idx = r * 256 + threadIdx.x;
        const int h2 = idx >> 8;
        const int d4 = idx & 255;
        const float* base = keys + (size_t)h2 * kD * kE + (size_t)(d4 * 4) * kE + e;
        float4 v;
        v.x = __ldg(base);
        v.y = __ldg(base + kE);
        v.z = __ldg(base + 2 * kE);
        v.w = __ldg(base + 3 * kE);
        kcol[idx] = v;
    }
    __syncthreads();
    const int warp = threadIdx.x >> 5;
    const int lane = threadIdx.x & 31;
    for (int tt = 0; tt < 16; tt++) {
        const int t = c * kN + warp * 16 + tt;
        float acc[8];
        #pragma unroll
        for (int i = 0; i < 8; i++) acc[i] = 0.f;
        const float4* xp = (const float4*)(xf + t * kD);
        #pragma unroll
        for (int i = 0; i < 8; i++) {
            const float4 xv = xp[i * 32 + lane];
            #pragma unroll
            for (int h2 = 0; h2 < 8; h2++) {
                const float4 kv = kcol[h2 * 256 + i * 32 + lane];
                acc[h2] += xv.x * kv.x + xv.y * kv.y + xv.z * kv.z + xv.w * kv.w;
            }
        }
        #pragma unroll
        for (int h2 = 0; h2 < 8; h2++) {
            float s = acc[h2];
            #pragma unroll
            for (int o = 16; o; o >>= 1) s += __shfl_xor_sync(0xffffffffu, s, o);
            if (lane == 0) G[((size_t)t * kET + j) * 8 + h2] = s;
        }
    }
}

// ---------------- K7: combine gate weights ----------------
__global__ void combine_kernel(const float* __restrict__ G,
                               const float* __restrict__ scores,
                               const int* __restrict__ indices,
                               const float* __restrict__ head_probs,
                               const float* __restrict__ score_probs,
                               float* __restrict__ wbuf) {
    const int tj = blockIdx.x * blockDim.x + threadIdx.x;  // T*ET
    if (tj >= kT * kET) return;
    const int t = tj >> 4, j = tj & 15;
    const int c = t >> 7;
    const int e = indices[c * kET + j];
    const int r = j >> 2;
    const float* sp0 = score_probs + ((size_t)(0 * kRE + r) * kE + e) * kH;
    const float* sp1 = score_probs + ((size_t)(1 * kRE + r) * kE + e) * kH + (size_t)0;
    // note: full offset for s=1 is (kRE*kE*kH) extra:
    sp1 = score_probs + (size_t)kRE * kE * kH + ((size_t)r * kE + e) * kH;
    const float* hp = head_probs + ((size_t)r * kE + e) * kH;
    const float* sc = scores + ((size_t)t * kET + j) * kH;
    const float* g = G + (size_t)tj * 8;
    float acc = 0.f;
    #pragma unroll
    for (int h = 0; h < kH; h++) {
        const float x = sp0[h] * g[h >> 1] + sp1[h] * sc[h];
        const float sig = 1.0f / (1.0f + __expf(-x));
        acc += sig * hp[h];
    }
    wbuf[tj] = acc;
}

// ---------------- K8: expert FFN + final residual ----------------
// block per token. warp w computes dots for j = 2w, 2w+1 (h0 and h1 each).
__global__ __launch_bounds__(256) void expert_kernel(const float* __restrict__ xf,
                                                     const float* __restrict__ experts,
                                                     const int* __restrict__ indices,
                                                     const float* __restrict__ wbuf,
                                                     const float* __restrict__ resid,
                                                     float* __restrict__ out) {
    const int t = blockIdx.x;
    const int c = t >> 7;
    __shared__ int es[kET];
    __shared__ float h01[2 * kET];
    __shared__ float act_s[kET];
    if (threadIdx.x < kET) es[threadIdx.x] = indices[c * kET + threadIdx.x];
    __syncthreads();
    const int warp = threadIdx.x >> 5;
    const int lane = threadIdx.x & 31;
    const float4* xp = (const float4*)(xf + t * kD);
    #pragma unroll
    for (int jj = 0; jj < 2; jj++) {
        const int j = warp * 2 + jj;
        const int e = es[j];
        const float4* w0 = (const float4*)(experts + ((size_t)0 * kE + e) * kD);
        const float4* w1 = (const float4*)(experts + ((size_t)1 * kE + e) * kD);
        float a0 = 0.f, a1 = 0.f;
        #pragma unroll
        for (int i = 0; i < 8; i++) {
            const float4 xv = xp[i * 32 + lane];
            const float4 v0 = w0[i * 32 + lane];
            const float4 v1 = w1[i * 32 + lane];
            a0 += xv.x * v0.x + xv.y * v0.y + xv.z * v0.z + xv.w * v0.w;
            a1 += xv.x * v1.x + xv.y * v1.y + xv.z * v1.z + xv.w * v1.w;
        }
        #pragma unroll
        for (int o = 16; o; o >>= 1) {
            a0 += __shfl_xor_sync(0xffffffffu, a0, o);
            a1 += __shfl_xor_sync(0xffffffffu, a1, o);
        }
        if (lane == 0) {
            h01[j] = a0;
            h01[kET + j] = a1;
        }
    }
    __syncthreads();
    if (threadIdx.x < kET) {
        const int j = threadIdx.x;
        const float h0 = h01[j], h1 = h01[kET + j];
        const float silu = h0 / (1.0f + __expf(-h0));
        act_s[j] = silu * h1 * wbuf[t * kET + j];
    }
    __syncthreads();
    float4 acc = ((const float4*)(resid + t * kD))[threadIdx.x];
    #pragma unroll
    for (int j = 0; j < kET; j++) {
        const float a = act_s[j];
        const float4 wv = ((const float4*)(experts + ((size_t)2 * kE + es[j]) * kD))[threadIdx.x];
        acc.x += a * wv.x; acc.y += a * wv.y; acc.z += a * wv.z; acc.w += a * wv.w;
    }
    ((float4*)(out + t * kD))[threadIdx.x] = acc;
}

// ---------------- launch ----------------
extern "C" void kernel_launch(void* const* d_in, const int* in_sizes, int n_in,
                              void* d_out, int out_size) {
    const float* x_input     = (const float*)d_in[0];
    const int*   indices     = (const int*)  d_in[1];
    const float* scores      = (const float*)d_in[2];
    const float* attn_w      = (const float*)d_in[3];
    const float* attn_out_w  = (const float*)d_in[4];
    const float* attn_norm_w = (const float*)d_in[5];
    const float* ffn_norm_w  = (const float*)d_in[6];
    const float* ffn_experts = (const float*)d_in[7];
    const float* keys        = (const float*)d_in[8];
    const float* head_probs  = (const float*)d_in[9];
    const float* score_probs = (const float*)d_in[10];
    float* out = (float*)d_out;

    float *xnorm, *qkv, *qr, *kr, *attn, *proj, *resid, *xf, *G, *wb;
    cudaGetSymbolAddress((void**)&xnorm, g_xnorm);
    cudaGetSymbolAddress((void**)&qkv,   g_qkv);
    cudaGetSymbolAddress((void**)&qr,    g_q);
    cudaGetSymbolAddress((void**)&kr,    g_k);
    cudaGetSymbolAddress((void**)&attn,  g_attn);
    cudaGetSymbolAddress((void**)&proj,  g_proj);
    cudaGetSymbolAddress((void**)&resid, g_resid);
    cudaGetSymbolAddress((void**)&xf,    g_xf);
    cudaGetSymbolAddress((void**)&G,     g_G);
    cudaGetSymbolAddress((void**)&wb,    g_w);

    rmsnorm_kernel<<<kT, 256>>>(x_input, attn_norm_w, xnorm);
    sgemm128<<<dim3(3 * kD / 128, kT / 128), 256>>>(kT, 3 * kD, kD, xnorm, attn_w, qkv);
    qkprep_kernel<<<kT, 256>>>(qkv, qr, kr);
    attn_kernel<<<dim3(kNH, kS / kQB), kQB>>>(qr, kr, qkv, attn);
    sgemm128<<<dim3(kD / 128, kT / 128), 256>>>(kT, kD, kD, attn, attn_out_w, proj);
    resid_rmsnorm_kernel<<<kT, 256>>>(proj, x_input, ffn_norm_w, resid, xf);
    route_gemm_kernel<<<dim3(kET, kBC), 256>>>(xf, keys, indices, G);
    combine_kernel<<<(kT * kET + 255) / 256, 256>>>(G, scores, indices, head_probs, score_probs, wb);
    expert_kernel<<<kT, 256>>>(xf, ffn_experts, indices, wb, resid, out);
}